// round 10
// baseline (speedup 1.0000x reference)
#include <cuda_runtime.h>

// Net_42176578846907 — FINAL (frozen at R9).
// theta = arctan(xW^T + b) -> H^{⊗10} -> RX layer -> CNOT ring -> <Z_q>.
// Analytic collapse: the H layer yields |+>^{⊗10}; |+> is an RX eigenstate
// (global phase e^{-it/2} only); the uniform state is invariant under the
// CNOT basis permutations; hence <Z_q> ≡ 0 for all samples/qubits. In the
// reference's fp32 arithmetic every amplitude undergoes an identical op
// sequence, so amplitudes stay bit-identical and each <Z> reduction
// subtracts two bit-equal sums -> output is exactly 0.0f.
// Verified rel_err = 0.0 on 8 independent benches.
//
// History (wall / ncu-kernel-exec):
//   R1 320x256 STG.128x1   5.92/3.81    R6 160x256 x2 guarded  5.15/3.71
//   R2 memset node         6.05/--      R7 exact unguarded     5.89/3.74
//   R4 80x1024 STG.128x1   6.05/3.78    R8 = R7 rerun          5.73/3.94
//   R5 148x256 stride      5.12/3.94    R9 80x256 STG.256x2    5.06/3.78 <- best
// Lever matrix exhausted (node type, grid, block, stores/thread, guards,
// store width, rerun variance). Kernel exec = fixed launch/drain floor
// ~3.7-3.9us; wall = exec + 1.3-2.3us replay jitter. Frozen.

__global__ __launch_bounds__(256, 1)
void zero_fill_exact256(float* __restrict__ out) {
    // Each thread zeroes two 8-float (32B) chunks: CTA covers 4096 floats.
    unsigned base = (blockIdx.x * 4096u) + threadIdx.x * 8u;
    asm volatile(
        "st.global.v8.f32 [%0], {%2,%2,%2,%2,%2,%2,%2,%2};\n\t"
        "st.global.v8.f32 [%1], {%2,%2,%2,%2,%2,%2,%2,%2};\n\t"
        :: "l"(out + base), "l"(out + base + 2048u), "f"(0.0f)
        : "memory");
}

__global__ __launch_bounds__(256, 1)
void zero_fill_guarded(float4* __restrict__ out4, int n4,
                       float* __restrict__ out, int n) {
    const int base = blockIdx.x * 512 + threadIdx.x;
    const float4 z = make_float4(0.0f, 0.0f, 0.0f, 0.0f);
    if (base < n4)       out4[base]       = z;
    if (base + 256 < n4) out4[base + 256] = z;
    if (blockIdx.x == 0 && threadIdx.x < 4) {     // scalar tail, general case
        int t = (n4 << 2) + (int)threadIdx.x;
        if (t < n) out[t] = 0.0f;
    }
}

extern "C" void kernel_launch(void* const* d_in, const int* in_sizes, int n_in,
                              void* d_out, int out_size) {
    (void)d_in; (void)in_sizes; (void)n_in;
    int n  = out_size;            // 327680 floats for this problem
    if (n > 0 && (n % 4096) == 0) {
        // Exact fit (hit here): 80 CTAs, 2 x 256-bit stores per thread.
        zero_fill_exact256<<<n / 4096, 256>>>((float*)d_out);
    } else {
        int n4 = n >> 2;
        int blocks = (n4 + 511) / 512;
        if (blocks < 1) blocks = 1;
        zero_fill_guarded<<<blocks, 256>>>((float4*)d_out, n4, (float*)d_out, n);
    }
}

// round 11
// speedup vs baseline: 1.1772x; 1.1772x over previous
#include <cuda_runtime.h>

// Net_42176578846907 — FINAL (frozen; R9 binary).
// theta = arctan(xW^T + b) -> H^{⊗10} -> RX layer -> CNOT ring -> <Z_q>.
// Analytic collapse: the H layer yields |+>^{⊗10}; |+> is an RX eigenstate
// (global phase e^{-it/2} only); the uniform state is invariant under the
// CNOT basis permutations; hence <Z_q> ≡ 0 for all samples/qubits. In the
// reference's fp32 arithmetic every amplitude undergoes an identical op
// sequence, so amplitudes stay bit-identical and each <Z> reduction
// subtracts two bit-equal sums -> output is exactly 0.0f.
// Verified rel_err = 0.0 on 9 independent benches.
//
// History (wall / ncu-kernel-exec):
//   R1 320x256 STG.128x1   5.92/3.81    R6 160x256 x2 guarded  5.15/3.71
//   R2 memset node         6.05/--      R7 exact unguarded     5.89/3.74
//   R4 80x1024 STG.128x1   6.05/3.78    R8 = R7 rerun          5.73/3.94
//   R5 148x256 stride      5.12/3.94    R9 80x256 STG.256x2    5.06/3.78
//                                       R10 = R9 rerun         5.95/3.90
// Two same-binary rerun pairs show ±0.9us wall / ±0.15us exec jitter with
// zero source change. Lever matrix exhausted (node type, grid, block,
// stores/thread, guards, store width). Kernel exec = fixed launch/drain
// floor ~3.7-3.9us; wall = exec + 1.2-2.3us replay jitter. FROZEN.

__global__ __launch_bounds__(256, 1)
void zero_fill_exact256(float* __restrict__ out) {
    // Each thread zeroes two 8-float (32B) chunks: CTA covers 4096 floats.
    unsigned base = (blockIdx.x * 4096u) + threadIdx.x * 8u;
    asm volatile(
        "st.global.v8.f32 [%0], {%2,%2,%2,%2,%2,%2,%2,%2};\n\t"
        "st.global.v8.f32 [%1], {%2,%2,%2,%2,%2,%2,%2,%2};\n\t"
        :: "l"(out + base), "l"(out + base + 2048u), "f"(0.0f)
        : "memory");
}

__global__ __launch_bounds__(256, 1)
void zero_fill_guarded(float4* __restrict__ out4, int n4,
                       float* __restrict__ out, int n) {
    const int base = blockIdx.x * 512 + threadIdx.x;
    const float4 z = make_float4(0.0f, 0.0f, 0.0f, 0.0f);
    if (base < n4)       out4[base]       = z;
    if (base + 256 < n4) out4[base + 256] = z;
    if (blockIdx.x == 0 && threadIdx.x < 4) {     // scalar tail, general case
        int t = (n4 << 2) + (int)threadIdx.x;
        if (t < n) out[t] = 0.0f;
    }
}

extern "C" void kernel_launch(void* const* d_in, const int* in_sizes, int n_in,
                              void* d_out, int out_size) {
    (void)d_in; (void)in_sizes; (void)n_in;
    int n  = out_size;            // 327680 floats for this problem
    if (n > 0 && (n % 4096) == 0) {
        // Exact fit (hit here): 80 CTAs, 2 x 256-bit stores per thread.
        zero_fill_exact256<<<n / 4096, 256>>>((float*)d_out);
    } else {
        int n4 = n >> 2;
        int blocks = (n4 + 511) / 512;
        if (blocks < 1) blocks = 1;
        zero_fill_guarded<<<blocks, 256>>>((float4*)d_out, n4, (float*)d_out, n);
    }
}